// round 5
// baseline (speedup 1.0000x reference)
#include <cuda_runtime.h>
#include <cuda_bf16.h>

#define N_IN    11008
#define N_OUT   4096
#define TOPK_K  5504
#define N_CACHE 64
#define NBW     ((N_IN + 31) / 32)   // 344 bitset words
#define NBLK    64                   // pre-work blocks (grid barrier participants)
#define NPREF   84                   // prefetch blocks (64+84 = 148 = #SMs)
#define SLICE   (N_IN / NBLK)        // 172 elements per pre-work block
#define PREF_J4 640                  // float4 per row prefix to prefetch (10KB/row)

// ---- device-global scratch (allocation-free) ----
__device__ __align__(16) float g_xm[N_IN];
__device__ unsigned g_maskbits[NBW];
__device__ unsigned g_hist0[2048];
__device__ unsigned g_hist1[2048];
__device__ unsigned g_hist2[1024];
__device__ int g_tiec[NBLK];
__device__ int g_inter[N_CACHE];
__device__ unsigned g_barcnt;        // monotonic grid-barrier counter (replay-safe)
__device__ float g_sink;             // DCE sink for prefetch

// Replay-safe grid barrier among the NBLK pre-work blocks only.
__device__ __forceinline__ void grid_barrier() {
    __syncthreads();
    if (threadIdx.x == 0) {
        __threadfence();
        unsigned old = atomicAdd(&g_barcnt, 1u);
        unsigned target = (old / NBLK + 1u) * NBLK;
        unsigned cur;
        do {
            asm volatile("ld.acquire.gpu.u32 %0, [%1];"
                         : "=r"(cur) : "l"(&g_barcnt) : "memory");
        } while (cur < target);
    }
    __syncthreads();
}

// Block-wide inclusive scan over 1024 threads (one int each).
__device__ __forceinline__ int block_incl_scan(int v, int lane, int wid, int* sbuf) {
    __syncthreads();
    #pragma unroll
    for (int o = 1; o < 32; o <<= 1) {
        int t = __shfl_up_sync(0xffffffffu, v, o);
        if (lane >= o) v += t;
    }
    if (lane == 31) sbuf[wid] = v;
    __syncthreads();
    if (wid == 0) {
        int w = sbuf[lane];
        #pragma unroll
        for (int o = 1; o < 32; o <<= 1) {
            int t = __shfl_up_sync(0xffffffffu, w, o);
            if (lane >= o) w += t;
        }
        sbuf[lane] = w;
    }
    __syncthreads();
    if (wid > 0) v += sbuf[wid - 1];
    return v;
}

// ============================================================================
// Fused kernel, grid = 148 blocks x 1024 threads (one per SM):
//   blocks [0,64):   distributed top-K select + recall + decision + xm build
//   blocks [64,148): L2 prefetch of the first PREF_J4 float4 of every W row
// ============================================================================
__global__ void __launch_bounds__(1024) fused_kernel(const float* __restrict__ x,
                                                     const int* __restrict__ cached,
                                                     const float* __restrict__ W) {
    const int tid  = threadIdx.x;
    const int lane = tid & 31, wid = tid >> 5;

    // ---------------- prefetch blocks: warm L2 with W row prefixes ----------
    if (blockIdx.x >= NBLK) {
        const float4* __restrict__ W4 = (const float4*)W;
        const int gw = (blockIdx.x - NBLK) * 32 + wid;   // 0..2687
        float s = 0.0f;
        for (int r = gw; r < N_OUT; r += (NPREF * 32)) {
            const float4* row = W4 + (long long)r * (N_IN / 4);
            #pragma unroll 4
            for (int j = lane; j < PREF_J4; j += 32) s += row[j].x;
        }
        if (s == 1.2345678e38f) g_sink = s;   // never true; keeps loads live
        return;
    }

    // ---------------- pre-work blocks ----------------
    __shared__ unsigned cbits[NBW];
    __shared__ int scanbuf[32];
    __shared__ int wsum[32];
    __shared__ int s_b, s_G, s_need, s_use, s_best, s_base;
    __shared__ unsigned s_T;

    const int b = blockIdx.x;
    const int base = b * SLICE;

    // Phase Z: zero global hists/mask slices; build dedup bitset for cache b.
    if (tid < 32) g_hist0[b * 32 + tid] = 0;
    else if (tid < 64) g_hist1[b * 32 + (tid - 32)] = 0;
    else if (tid < 80) g_hist2[b * 16 + (tid - 64)] = 0;
    for (int i = tid; i < NBW; i += 1024)
        if ((i & 63) == b) g_maskbits[i] = 0;

    for (int i = tid; i < NBW; i += 1024) cbits[i] = 0;
    __syncthreads();
    {
        const int* row = cached + b * TOPK_K;
        for (int k = tid; k < TOPK_K; k += 1024) {
            int idx = row[k];
            atomicOr(&cbits[idx >> 5], 1u << (idx & 31));
        }
    }

    grid_barrier();   // B0: hists zeroed everywhere

    // This block's slice element (one per thread; SLICE=172 < 1024).
    unsigned u = 0;
    float xv = 0.0f;
    if (tid < SLICE) {
        xv = x[base + tid];
        u = __float_as_uint(xv) & 0x7FFFFFFFu;
    }

    // ---- level 0 fill: bits [30:21] ----
    if (tid < SLICE) atomicAdd(&g_hist0[u >> 21], 1u);
    grid_barrier();   // B1

    // ---- level 0 search (redundant per block) ----
    {
        const int j0 = 2047 - 2 * tid, j1 = j0 - 1;
        const int h0 = g_hist0[j0], h1 = g_hist0[j1];
        int S = block_incl_scan(h0 + h1, lane, wid, scanbuf);
        int excl = S - h0 - h1;
        const int Kr = TOPK_K;
        if (excl + h0 >= Kr && excl < Kr)   { s_b = j0; s_G = excl; }
        else if (S >= Kr && excl + h0 < Kr) { s_b = j1; s_G = excl + h0; }
    }
    __syncthreads();
    const int b0 = s_b, G0 = s_G;

    // ---- level 1 fill: bits [20:10] ----
    if (tid < SLICE && (int)(u >> 21) == b0)
        atomicAdd(&g_hist1[(u >> 10) & 0x7FF], 1u);
    grid_barrier();   // B2

    {
        const int j0 = 2047 - 2 * tid, j1 = j0 - 1;
        const int h0 = g_hist1[j0], h1 = g_hist1[j1];
        int S = block_incl_scan(h0 + h1, lane, wid, scanbuf);
        int excl = S - h0 - h1;
        const int Kr = TOPK_K - G0;
        if (excl + h0 >= Kr && excl < Kr)   { s_b = j0; s_G = G0 + excl; }
        else if (S >= Kr && excl + h0 < Kr) { s_b = j1; s_G = G0 + excl + h0; }
    }
    __syncthreads();
    const int b1 = s_b, G1 = s_G;

    // ---- level 2 fill: bits [9:0] ----
    const unsigned top22 = ((unsigned)b0 << 21) | ((unsigned)b1 << 10);
    if (tid < SLICE && (u & 0xFFFFFC00u) == top22)
        atomicAdd(&g_hist2[u & 0x3FF], 1u);
    grid_barrier();   // B3

    {
        const int j = 1023 - tid;
        const int h = g_hist2[j];
        int S = block_incl_scan(h, lane, wid, scanbuf);
        int excl = S - h;
        const int Kr = TOPK_K - G1;
        if (S >= Kr && excl < Kr) { s_T = top22 | (unsigned)j; s_need = Kr - excl; }
    }
    __syncthreads();
    const unsigned T = s_T;
    const int need = s_need;

    // ---- tie counting (global rank by index = block order then tid order) ----
    int tie = (tid < SLICE && u == T) ? 1 : 0;
    int incl = block_incl_scan(tie, lane, wid, scanbuf);
    const int rank_in_blk = incl - tie;
    if (tid == 1023) g_tiec[b] = incl;   // block total
    grid_barrier();   // B4

    if (tid == 0) {
        int s = 0;
        for (int i = 0; i < b; i++) s += g_tiec[i];
        s_base = s;
    }
    __syncthreads();

    int sel = 0;
    if (tid < SLICE) {
        if (u > T) sel = 1;
        else if (tie) sel = (s_base + rank_in_blk < need);
        if (sel) atomicOr(&g_maskbits[(base + tid) >> 5], 1u << ((base + tid) & 31));
    }
    grid_barrier();   // B5: g_maskbits final

    // ---- intersection (deduped) ----
    int cnt = 0;
    for (int i = tid; i < NBW; i += 1024) cnt += __popc(cbits[i] & g_maskbits[i]);
    #pragma unroll
    for (int o = 16; o; o >>= 1) cnt += __shfl_down_sync(0xffffffffu, cnt, o);
    if (lane == 0) wsum[wid] = cnt;
    __syncthreads();
    if (tid == 0) {
        int s = 0;
        #pragma unroll
        for (int i = 0; i < 32; i++) s += wsum[i];
        g_inter[b] = s;
    }
    grid_barrier();   // B6: g_inter published

    // ---- decision (redundant per block) + xm slice build ----
    if (tid == 0) {
        float best = -1.0f; int bi = 0;
        #pragma unroll
        for (int i = 0; i < N_CACHE; i++) {
            float r = (float)g_inter[i] / (float)TOPK_K;
            if (r > best) { best = r; bi = i; }   // first-max = argmax
        }
        s_use  = (best >= 0.9f) ? 1 : 0;
        s_best = bi;
    }
    __syncthreads();

    if (!s_use) {
        if (tid < SLICE) g_xm[base + tid] = sel ? xv : 0.0f;
    } else {
        if (tid < SLICE) g_xm[base + tid] = 0.0f;
        grid_barrier();                          // B7: all of xm zeroed
        const int kbase = b * (TOPK_K / NBLK);   // 86 per block
        const int* brow = cached + s_best * TOPK_K;
        for (int k = kbase + tid; k < kbase + TOPK_K / NBLK; k += 1024) {
            int idx = brow[k];
            atomicAdd(&g_xm[idx], x[idx]);       // duplicates = multiplicity
        }
    }
}

// ============================================================================
// GEMV: out = W @ xm + bias. Warp-per-row, float4, streaming hint on W.
// 180 MB of W (42 MB pre-warmed in L2) = the memory roofline.
// ============================================================================
__global__ void __launch_bounds__(256) gemv_kernel(const float* __restrict__ W,
                                                   const float* __restrict__ bias,
                                                   float* __restrict__ out) {
    const int row  = (blockIdx.x * 256 + threadIdx.x) >> 5;
    const int lane = threadIdx.x & 31;

    const float4* __restrict__ w4 = (const float4*)(W + (long long)row * N_IN);
    const float4* __restrict__ x4 = (const float4*)g_xm;

    float a0 = 0.0f, a1 = 0.0f;
    // N_IN/4 = 2752 = 43 * 64: two float4 per lane per iteration.
    #pragma unroll 4
    for (int it = 0; it < 43; it++) {
        const int j = lane + it * 64;
        float4 w  = __ldcs(w4 + j);
        float4 v  = x4[j];
        a0 += w.x * v.x + w.y * v.y;
        a1 += w.z * v.z + w.w * v.w;
        float4 w2 = __ldcs(w4 + j + 32);
        float4 v2 = x4[j + 32];
        a0 += w2.x * v2.x + w2.y * v2.y;
        a1 += w2.z * v2.z + w2.w * v2.w;
    }
    float acc = a0 + a1;
    #pragma unroll
    for (int o = 16; o; o >>= 1) acc += __shfl_down_sync(0xffffffffu, acc, o);
    if (lane == 0) out[row] = acc + bias[row];
}

// ============================================================================
extern "C" void kernel_launch(void* const* d_in, const int* in_sizes, int n_in,
                              void* d_out, int out_size) {
    const float* x      = (const float*)d_in[0];
    const float* W      = (const float*)d_in[1];
    const float* bias   = (const float*)d_in[2];
    const int*   cached = (const int*)d_in[3];
    float*       out    = (float*)d_out;

    fused_kernel<<<NBLK + NPREF, 1024>>>(x, cached, W);
    gemv_kernel<<<(N_OUT * 32) / 256, 256>>>(W, bias, out);
}